// round 10
// baseline (speedup 1.0000x reference)
#include <cuda_runtime.h>
#include <cuda_bf16.h>
#include <math.h>
#include <stdint.h>

#define T_STEPS 1024
#define NCTA 128
#define SPS 544   // sPart per-ksplit stride (floats): 32 rows * 17

// -------- packed fp32x2 helpers --------
__device__ __forceinline__ unsigned long long pack2(float x) {
    unsigned long long r; asm("mov.b64 %0, {%1, %1};" : "=l"(r) : "f"(x)); return r;
}
__device__ __forceinline__ void fma2(unsigned long long &d, unsigned long long a, unsigned long long b) {
    asm("fma.rn.f32x2 %0, %1, %2, %0;" : "+l"(d) : "l"(a), "l"(b));
}
__device__ __forceinline__ float2 unpack2(unsigned long long v) {
    float2 r; asm("mov.b64 {%0, %1}, %2;" : "=f"(r.x), "=f"(r.y) : "l"(v)); return r;
}

// -------- scratch (static device globals) --------
__device__ float g_xproj[(size_t)16384 * 4096];       // 256 MB
__device__ float g_hs[(size_t)16 * 1024 * 1024];      // 64 MB [b][t][h]
__device__ float g_hbuf[2][16384];                    // h double buffer [k][b]
__device__ int   g_flags[NCTA * 8];
__device__ unsigned int g_bar_count;
__device__ volatile unsigned int g_bar_gen;
__device__ __nv_bfloat16 g_A3[(size_t)16384 * 3072];  // 96 MB
__device__ __nv_bfloat16 g_W3[(size_t)4096 * 3072];   // 24 MB

// -------- software grid barrier (init only; replay-safe) --------
__device__ __forceinline__ void grid_barrier() {
    __syncthreads();
    if (threadIdx.x == 0) {
        __threadfence();
        unsigned int gen = g_bar_gen;
        unsigned int t = atomicAdd(&g_bar_count, 1u);
        if (t == NCTA - 1) {
            g_bar_count = 0u;
            __threadfence();
            g_bar_gen = gen + 1u;
        } else {
            while (g_bar_gen == gen) { }
            __threadfence();
        }
    }
    __syncthreads();
}

// -------- cp.async helpers --------
__device__ __forceinline__ uint32_t smem_u32(const void* p) {
    uint32_t a;
    asm("{ .reg .u64 t; cvta.to.shared.u64 t, %1; cvt.u32.u64 %0, t; }" : "=r"(a) : "l"(p));
    return a;
}
__device__ __forceinline__ void cp16(uint32_t dst, const void* src) {
    asm volatile("cp.async.cg.shared.global [%0], [%1], 16;" :: "r"(dst), "l"(src));
}
__device__ __forceinline__ void cp_commit() { asm volatile("cp.async.commit_group;"); }
template <int N>
__device__ __forceinline__ void cp_wait() { asm volatile("cp.async.wait_group %0;" :: "n"(N)); }

// -------- mma.sync bf16 --------
__device__ __forceinline__ void mma_bf16(float* c, const uint32_t* a, uint32_t b0, uint32_t b1) {
    asm volatile(
        "mma.sync.aligned.m16n8k16.row.col.f32.bf16.bf16.f32 "
        "{%0,%1,%2,%3}, {%4,%5,%6,%7}, {%8,%9}, {%0,%1,%2,%3};"
        : "+f"(c[0]), "+f"(c[1]), "+f"(c[2]), "+f"(c[3])
        : "r"(a[0]), "r"(a[1]), "r"(a[2]), "r"(a[3]), "r"(b0), "r"(b1));
}

// ===================================================================
// split3: fp32 [M][1024] -> bf16 [M][3072] split-concat (xproj prep)
// ===================================================================
__global__ __launch_bounds__(256) void split3(
    const float* __restrict__ src, __nv_bfloat16* __restrict__ dst,
    int off2, int off3, int seq_layout)
{
    size_t m = blockIdx.x;
    int k = threadIdx.x * 4;
    size_t si = seq_layout ? ((size_t)(m & 15) * 1048576 + (size_t)(m >> 4) * 1024 + k)
                           : (m * 1024 + k);
    float4 v = *(const float4*)(src + si);
    __nv_bfloat16 h0 = __float2bfloat16(v.x), h1 = __float2bfloat16(v.y);
    __nv_bfloat16 h2 = __float2bfloat16(v.z), h3 = __float2bfloat16(v.w);
    __nv_bfloat162 H0 = __halves2bfloat162(h0, h1), H1 = __halves2bfloat162(h2, h3);
    __nv_bfloat162 L0 = __halves2bfloat162(__float2bfloat16(v.x - __bfloat162float(h0)),
                                           __float2bfloat16(v.y - __bfloat162float(h1)));
    __nv_bfloat162 L1 = __halves2bfloat162(__float2bfloat16(v.z - __bfloat162float(h2)),
                                           __float2bfloat16(v.w - __bfloat162float(h3)));
    __nv_bfloat16* base = dst + m * 3072;
    *(__nv_bfloat162*)(base + k) = H0;          *(__nv_bfloat162*)(base + k + 2) = H1;
    *(__nv_bfloat162*)(base + off2 + k) = H0;   *(__nv_bfloat162*)(base + off2 + k + 2) = H1;
    *(__nv_bfloat162*)(base + off3 + k) = L0;   *(__nv_bfloat162*)(base + off3 + k + 2) = L1;
}

// ===================================================================
// Phase A HMMA GEMM — unchanged from R6/R8 (known good)
// ===================================================================
#define BK 32
#define KIT 96
__global__ __launch_bounds__(256, 2) void hmma_gemm(const float* __restrict__ bias, int bias_off)
{
    __shared__ __align__(16) __nv_bfloat16 As[2][128 * 40];
    __shared__ __align__(16) __nv_bfloat16 Bs[2][128 * 40];

    int tid = threadIdx.x;
    int n0 = blockIdx.x * 128, m0 = blockIdx.y * 128;
    int warp = tid >> 5, lane = tid & 31;
    int wm = (warp & 1) * 64, wn = (warp >> 1) * 32;
    int g = lane >> 2, q = lane & 3;

    int srow = tid >> 1;
    int scol = (tid & 1) * 16;
    const __nv_bfloat16* gA = g_A3 + (size_t)(m0 + srow) * 3072 + scol;
    const __nv_bfloat16* gB = g_W3 + (size_t)(n0 + srow) * 3072 + scol;
    uint32_t sAd[2], sBd[2];
    sAd[0] = smem_u32(&As[0][srow * 40 + scol]);
    sAd[1] = smem_u32(&As[1][srow * 40 + scol]);
    sBd[0] = smem_u32(&Bs[0][srow * 40 + scol]);
    sBd[1] = smem_u32(&Bs[1][srow * 40 + scol]);

    float acc[4][4][4];
#pragma unroll
    for (int i = 0; i < 4; i++)
#pragma unroll
        for (int j = 0; j < 4; j++)
#pragma unroll
            for (int r = 0; r < 4; r++) acc[i][j][r] = 0.f;

    cp16(sAd[0], gA);      cp16(sAd[0] + 16, gA + 8);
    cp16(sBd[0], gB);      cp16(sBd[0] + 16, gB + 8);
    cp_commit();

    for (int c = 0; c < KIT; c++) {
        int buf = c & 1;
        if (c + 1 < KIT) {
            int nb = (c + 1) & 1;
            const __nv_bfloat16* a = gA + (c + 1) * BK;
            const __nv_bfloat16* b = gB + (c + 1) * BK;
            cp16(sAd[nb], a);      cp16(sAd[nb] + 16, a + 8);
            cp16(sBd[nb], b);      cp16(sBd[nb] + 16, b + 8);
            cp_commit();
            cp_wait<1>();
        } else {
            cp_wait<0>();
        }
        __syncthreads();

        const __nv_bfloat16* Ab = As[buf];
        const __nv_bfloat16* Bb = Bs[buf];
#pragma unroll
        for (int kk = 0; kk < 32; kk += 16) {
            uint32_t af[4][4];
#pragma unroll
            for (int i = 0; i < 4; i++) {
                const __nv_bfloat16* p = Ab + (wm + i * 16 + g) * 40 + kk + 2 * q;
                af[i][0] = *(const uint32_t*)p;
                af[i][1] = *(const uint32_t*)(p + 8 * 40);
                af[i][2] = *(const uint32_t*)(p + 8);
                af[i][3] = *(const uint32_t*)(p + 8 * 40 + 8);
            }
#pragma unroll
            for (int j = 0; j < 4; j++) {
                const __nv_bfloat16* p = Bb + (wn + j * 8 + g) * 40 + kk + 2 * q;
                uint32_t b0 = *(const uint32_t*)p;
                uint32_t b1 = *(const uint32_t*)(p + 8);
#pragma unroll
                for (int i = 0; i < 4; i++)
                    mma_bf16(acc[i][j], af[i], b0, b1);
            }
        }
        __syncthreads();
    }

#pragma unroll
    for (int j = 0; j < 4; j++) {
        int n = n0 + wn + j * 8 + 2 * q;
        float b0 = __ldg(bias + bias_off + n);
        float b1 = __ldg(bias + bias_off + n + 1);
#pragma unroll
        for (int i = 0; i < 4; i++) {
            int m = m0 + wm + i * 16 + g;
            float2 v0 = { acc[i][j][0] + b0, acc[i][j][1] + b1 };
            float2 v1 = { acc[i][j][2] + b0, acc[i][j][3] + b1 };
            *(float2*)(g_xproj + (size_t)m * 4096 + n) = v0;
            *(float2*)(g_xproj + (size_t)(m + 8) * 4096 + n) = v1;
        }
    }
}

// ===================================================================
// Phase B: persistent sLSTM recurrence, 1024 threads (32 warps).
// CTA j owns h-units [8j, 8j+8) => 32 gate rows.
// warp = (ksplit 0-15 [64 k], bhalf 0-1 [8 b]); lane = gate row.
// R in SMEM transposed [k][row]: lane-distinct LDS.32, full crossbar.
// h: each warp stages + reads only its own b-half (disjoint, no sync).
// SMEM: sR 128K + sH 64K + sPart 34.8K = 231,424 B.
// ===================================================================
__global__ __launch_bounds__(1024, 1) void slstm_rec(const float* __restrict__ Rl)
{
    extern __shared__ float smem[];
    float* sR    = smem;                 // [1024][32]  k*32 + row
    float* sH    = smem + 32768;         // [1024][16]
    float* sPart = smem + 49152;         // [16][SPS]   ks*SPS + row*17 + b

    int tid = threadIdx.x;
    int wid = tid >> 5;
    int ks = wid >> 1;           // 0..15
    int bh = wid & 1;            // 0..1
    int lane = tid & 31;         // gate row
    int u_base = blockIdx.x * 8;

    if (tid == 0) g_flags[blockIdx.x * 8] = 0;
    grid_barrier();

    // ---- stage R transposed into smem (once): sR[k*32 + row] ----
    for (int idx = tid; idx < 8192; idx += 1024) {
        int row = idx & 31;
        int k4 = idx >> 5;           // 0..255
        int grow = (row >> 3) * 1024 + u_base + (row & 7);
        float4 v = *(const float4*)(Rl + (size_t)grow * 1024 + k4 * 4);
        sR[(k4 * 4 + 0) * 32 + row] = v.x;
        sR[(k4 * 4 + 1) * 32 + row] = v.y;
        sR[(k4 * 4 + 2) * 32 + row] = v.z;
        sR[(k4 * 4 + 3) * 32 + row] = v.w;
    }
    // h0 = 0
    for (int i = tid; i < 16384; i += 1024) sH[i] = 0.f;
    __syncthreads();

    // pointwise mapping (tid < 128): b = tid&15, u = tid>>4
    int pb = tid & 15, pu = tid >> 4;
    float creg = 0.f, nreg = 1.f, mreg = 0.f;

    const float* rk = sR + ks * 64 * 32 + lane;
    const float* hk = sH + ks * 64 * 16 + bh * 8;
    float* pp = sPart + ks * SPS + lane * 17 + bh * 8;
    const int* myflag = g_flags + (8 * ks + (lane & 7)) * 8;

    for (int t = 0; t < T_STEPS; t++) {
        // prefetch x_proj for this step
        float xpre[4];
        if (tid < 128) {
            const float* xp = g_xproj + ((size_t)t * 16 + pb) * 4096 + u_base + pu;
            xpre[0] = __ldg(xp);
            xpre[1] = __ldg(xp + 1024);
            xpre[2] = __ldg(xp + 2048);
            xpre[3] = __ldg(xp + 3072);
        }

        if (t > 0) {
            // wait for my 8 producers
            for (;;) {
                int f;
                asm volatile("ld.acquire.gpu.global.b32 %0, [%1];" : "=r"(f) : "l"(myflag));
                if (__all_sync(0xffffffffu, f >= t)) break;
            }
            // stage my (ks, b-half): 64 k x 32B, disjoint per warp
            const float* gsrc = g_hbuf[(t - 1) & 1];
#pragma unroll
            for (int j = 0; j < 4; j++) {
                int e = j * 32 + lane;           // 0..127
                int k = e >> 1, half = e & 1;
                const float4* s4 = (const float4*)(gsrc + (ks * 64 + k) * 16 + bh * 8 + half * 4);
                float4 v = __ldcg(s4);
                *(float4*)(sH + (ks * 64 + k) * 16 + bh * 8 + half * 4) = v;
            }
            __syncwarp();
        }

        // ---- GEMM: acc[4] (8 b as f32x2) over my 64 k ----
        unsigned long long acc[4];
        acc[0] = 0ull; acc[1] = 0ull; acc[2] = 0ull; acc[3] = 0ull;
#pragma unroll
        for (int k = 0; k < 64; k++) {
            unsigned long long rp = pack2(rk[k * 32]);
            ulonglong2 ha = *(const ulonglong2*)(hk + k * 16);
            ulonglong2 hb2 = *(const ulonglong2*)(hk + k * 16 + 4);
            fma2(acc[0], rp, ha.x);  fma2(acc[1], rp, ha.y);
            fma2(acc[2], rp, hb2.x); fma2(acc[3], rp, hb2.y);
        }

        // ---- store partials (scalar STS, stride-17 rows: conflict-free) ----
        {
            float2 a0 = unpack2(acc[0]), a1 = unpack2(acc[1]);
            float2 a2 = unpack2(acc[2]), a3 = unpack2(acc[3]);
            pp[0] = a0.x; pp[1] = a0.y; pp[2] = a1.x; pp[3] = a1.y;
            pp[4] = a2.x; pp[5] = a2.y; pp[6] = a3.x; pp[7] = a3.y;
        }
        __syncthreads();   // BAR_A: partials ready

        // ---- merged reduce + pointwise (128 threads) ----
        if (tid < 128) {
            float pre[4];
#pragma unroll
            for (int g4 = 0; g4 < 4; g4++) {
                float s = xpre[g4];
                const float* qp = sPart + (g4 * 8 + pu) * 17 + pb;
#pragma unroll
                for (int k2 = 0; k2 < 16; k2++) s += qp[k2 * SPS];
                pre[g4] = s;
            }
            float ez = __expf(2.f * pre[0]);
            float z = __fdividef(ez - 1.f, ez + 1.f);
            float o = __fdividef(1.f, 1.f + __expf(-pre[3]));
            float mn = fmaxf(pre[2] + mreg, pre[1]);
            float ip = __expf(pre[1] - mn);
            float fp = __expf(pre[2] + mreg - mn);
            creg = fp * creg + ip * z;
            nreg = fp * nreg + ip;
            mreg = mn;
            float h = o * __fdividef(creg, nreg);
            g_hbuf[t & 1][(u_base + pu) * 16 + pb] = h;
            g_hs[(size_t)pb * 1048576 + (size_t)t * 1024 + u_base + pu] = h;
        }
        __syncthreads();   // BAR_B: h stored, sPart consumed
        if (tid == 0) {
            __threadfence();
            g_flags[blockIdx.x * 8] = t + 1;
        }
    }
}

// ===================================================================
// Final projection: h_last in g_hbuf[(T_STEPS-1)&1] = g_hbuf[1]
// ===================================================================
__global__ __launch_bounds__(256) void final_out(
    const float* __restrict__ Wout, const float* __restrict__ bout,
    float* __restrict__ out)
{
    const float* hsrc = g_hbuf[(T_STEPS - 1) & 1];
    int o = (blockIdx.x * blockDim.x + threadIdx.x) >> 5;
    int lane = threadIdx.x & 31;
    const float* wr = Wout + (size_t)o * 1024;
    float acc[16];
#pragma unroll
    for (int b = 0; b < 16; b++) acc[b] = 0.f;
    for (int k = lane; k < 1024; k += 32) {
        float w = wr[k];
        const float4* hp = (const float4*)(hsrc + k * 16);
        float4 h0 = hp[0], h1 = hp[1], h2 = hp[2], h3 = hp[3];
        acc[0]  += w * h0.x; acc[1]  += w * h0.y; acc[2]  += w * h0.z; acc[3]  += w * h0.w;
        acc[4]  += w * h1.x; acc[5]  += w * h1.y; acc[6]  += w * h1.z; acc[7]  += w * h1.w;
        acc[8]  += w * h2.x; acc[9]  += w * h2.y; acc[10] += w * h2.z; acc[11] += w * h2.w;
        acc[12] += w * h3.x; acc[13] += w * h3.y; acc[14] += w * h3.z; acc[15] += w * h3.w;
    }
#pragma unroll
    for (int b = 0; b < 16; b++) {
#pragma unroll
        for (int off = 16; off; off >>= 1)
            acc[b] += __shfl_down_sync(0xffffffffu, acc[b], off);
    }
    if (lane == 0) {
        float bo = bout[o];
#pragma unroll
        for (int b = 0; b < 16; b++)
            out[(size_t)b * 1024 + o] = acc[b] + bo;
    }
}

// ===================================================================
extern "C" void kernel_launch(void* const* d_in, const int* in_sizes, int n_in,
                              void* d_out, int out_size)
{
    const float* x    = (const float*)d_in[0];
    const float* W    = (const float*)d_in[1];
    const float* R    = (const float*)d_in[2];
    const float* bias = (const float*)d_in[3];
    const float* Wout = (const float*)d_in[4];
    const float* bout = (const float*)d_in[5];
    float* out = (float*)d_out;

    const int REC_SMEM = (32768 + 16384 + 16 * SPS) * 4;   // 231,424 B
    cudaFuncSetAttribute(slstm_rec, cudaFuncAttributeMaxDynamicSharedMemorySize, REC_SMEM);

    __nv_bfloat16 *ga3, *gw3;
    float *ghs;
    cudaGetSymbolAddress((void**)&ga3, g_A3);
    cudaGetSymbolAddress((void**)&gw3, g_W3);
    cudaGetSymbolAddress((void**)&ghs, g_hs);

    dim3 tgrid(32, 128);
    // ---- layer 0 ----
    split3<<<4096, 256>>>(W, gw3, 1024, 2048, 0);
    split3<<<16384, 256>>>(x, ga3, 2048, 1024, 1);
    hmma_gemm<<<tgrid, 256>>>(bias, 0);
    slstm_rec<<<NCTA, 1024, REC_SMEM>>>(R);
    // ---- layer 1 ----
    split3<<<4096, 256>>>(W + (size_t)4096 * 1024, gw3, 1024, 2048, 0);
    split3<<<16384, 256>>>(ghs, ga3, 2048, 1024, 1);
    hmma_gemm<<<tgrid, 256>>>(bias, 4096);
    slstm_rec<<<NCTA, 1024, REC_SMEM>>>(R + (size_t)4096 * 1024);
    // ---- output ----
    final_out<<<128, 256>>>(Wout, bout, out);
}

// round 11
// speedup vs baseline: 1.2336x; 1.2336x over previous
#include <cuda_runtime.h>
#include <cuda_bf16.h>
#include <math.h>
#include <stdint.h>

#define T_STEPS 1024
#define NCTA 128
#define PS 584   // sPart per-ksplit stride (floats)

// -------- packed fp32x2 helpers --------
__device__ __forceinline__ unsigned long long pack2(float x) {
    unsigned long long r; asm("mov.b64 %0, {%1, %1};" : "=l"(r) : "f"(x)); return r;
}
__device__ __forceinline__ void fma2(unsigned long long &d, unsigned long long a, unsigned long long b) {
    asm("fma.rn.f32x2 %0, %1, %2, %0;" : "+l"(d) : "l"(a), "l"(b));
}

// -------- scratch (static device globals) --------
__device__ float g_xproj[(size_t)16384 * 4096];       // 256 MB
__device__ float g_hs[(size_t)16 * 1024 * 1024];      // 64 MB [b][t][h]
__device__ float g_hbuf[2][16384];                    // h double buffer [k][b]
__device__ int   g_flags[NCTA * 8];
__device__ unsigned int g_bar_count;
__device__ volatile unsigned int g_bar_gen;
__device__ __nv_bfloat16 g_A3[(size_t)16384 * 3072];  // 96 MB
__device__ __nv_bfloat16 g_W3[(size_t)4096 * 3072];   // 24 MB

// -------- software grid barrier (init only; replay-safe) --------
__device__ __forceinline__ void grid_barrier() {
    __syncthreads();
    if (threadIdx.x == 0) {
        __threadfence();
        unsigned int gen = g_bar_gen;
        unsigned int t = atomicAdd(&g_bar_count, 1u);
        if (t == NCTA - 1) {
            g_bar_count = 0u;
            __threadfence();
            g_bar_gen = gen + 1u;
        } else {
            while (g_bar_gen == gen) { }
            __threadfence();
        }
    }
    __syncthreads();
}

// -------- cp.async helpers --------
__device__ __forceinline__ uint32_t smem_u32(const void* p) {
    uint32_t a;
    asm("{ .reg .u64 t; cvta.to.shared.u64 t, %1; cvt.u32.u64 %0, t; }" : "=r"(a) : "l"(p));
    return a;
}
__device__ __forceinline__ void cp16(uint32_t dst, const void* src) {
    asm volatile("cp.async.cg.shared.global [%0], [%1], 16;" :: "r"(dst), "l"(src));
}
__device__ __forceinline__ void cp_commit() { asm volatile("cp.async.commit_group;"); }
template <int N>
__device__ __forceinline__ void cp_wait() { asm volatile("cp.async.wait_group %0;" :: "n"(N)); }

// -------- mma.sync bf16 --------
__device__ __forceinline__ void mma_bf16(float* c, const uint32_t* a, uint32_t b0, uint32_t b1) {
    asm volatile(
        "mma.sync.aligned.m16n8k16.row.col.f32.bf16.bf16.f32 "
        "{%0,%1,%2,%3}, {%4,%5,%6,%7}, {%8,%9}, {%0,%1,%2,%3};"
        : "+f"(c[0]), "+f"(c[1]), "+f"(c[2]), "+f"(c[3])
        : "r"(a[0]), "r"(a[1]), "r"(a[2]), "r"(a[3]), "r"(b0), "r"(b1));
}

// ===================================================================
// split3: fp32 [M][1024] -> bf16 [M][3072] split-concat (xproj prep)
// ===================================================================
__global__ __launch_bounds__(256) void split3(
    const float* __restrict__ src, __nv_bfloat16* __restrict__ dst,
    int off2, int off3, int seq_layout)
{
    size_t m = blockIdx.x;
    int k = threadIdx.x * 4;
    size_t si = seq_layout ? ((size_t)(m & 15) * 1048576 + (size_t)(m >> 4) * 1024 + k)
                           : (m * 1024 + k);
    float4 v = *(const float4*)(src + si);
    __nv_bfloat16 h0 = __float2bfloat16(v.x), h1 = __float2bfloat16(v.y);
    __nv_bfloat16 h2 = __float2bfloat16(v.z), h3 = __float2bfloat16(v.w);
    __nv_bfloat162 H0 = __halves2bfloat162(h0, h1), H1 = __halves2bfloat162(h2, h3);
    __nv_bfloat162 L0 = __halves2bfloat162(__float2bfloat16(v.x - __bfloat162float(h0)),
                                           __float2bfloat16(v.y - __bfloat162float(h1)));
    __nv_bfloat162 L1 = __halves2bfloat162(__float2bfloat16(v.z - __bfloat162float(h2)),
                                           __float2bfloat16(v.w - __bfloat162float(h3)));
    __nv_bfloat16* base = dst + m * 3072;
    *(__nv_bfloat162*)(base + k) = H0;          *(__nv_bfloat162*)(base + k + 2) = H1;
    *(__nv_bfloat162*)(base + off2 + k) = H0;   *(__nv_bfloat162*)(base + off2 + k + 2) = H1;
    *(__nv_bfloat162*)(base + off3 + k) = L0;   *(__nv_bfloat162*)(base + off3 + k + 2) = L1;
}

// ===================================================================
// Phase A HMMA GEMM, 4-stage cp.async pipeline, 1 sync/iter.
// C[16384,4096] = A3 · W3^T + bias.  128x128 tile, 8 warps 64x32.
// Dyn smem: As[4] + Bs[4], tile = 128*40 bf16 = 10240 B -> 81920 B.
// ===================================================================
#define BK 32
#define KIT 96
#define TILE_B 10240
__global__ __launch_bounds__(256, 2) void hmma_gemm(const float* __restrict__ bias, int bias_off)
{
    extern __shared__ __align__(16) char gsm[];
    __nv_bfloat16* As = (__nv_bfloat16*)gsm;                    // 4 stages
    __nv_bfloat16* Bs = (__nv_bfloat16*)(gsm + 4 * TILE_B);    // 4 stages

    int tid = threadIdx.x;
    int n0 = blockIdx.x * 128, m0 = blockIdx.y * 128;
    int warp = tid >> 5, lane = tid & 31;
    int wm = (warp & 1) * 64, wn = (warp >> 1) * 32;
    int g = lane >> 2, q = lane & 3;

    int srow = tid >> 1;
    int scol = (tid & 1) * 16;
    const __nv_bfloat16* gA = g_A3 + (size_t)(m0 + srow) * 3072 + scol;
    const __nv_bfloat16* gB = g_W3 + (size_t)(n0 + srow) * 3072 + scol;
    uint32_t sOff = (srow * 40 + scol) * 2;   // byte offset within a tile
    uint32_t aBase = smem_u32(As), bBase = smem_u32(Bs);

    float acc[4][4][4];
#pragma unroll
    for (int i = 0; i < 4; i++)
#pragma unroll
        for (int j = 0; j < 4; j++)
#pragma unroll
            for (int r = 0; r < 4; r++) acc[i][j][r] = 0.f;

    // prologue: stages 0,1,2
#pragma unroll
    for (int s = 0; s < 3; s++) {
        const __nv_bfloat16* a = gA + s * BK;
        const __nv_bfloat16* b = gB + s * BK;
        cp16(aBase + s * TILE_B + sOff, a);  cp16(aBase + s * TILE_B + sOff + 16, a + 8);
        cp16(bBase + s * TILE_B + sOff, b);  cp16(bBase + s * TILE_B + sOff + 16, b + 8);
        cp_commit();
    }

    for (int c = 0; c < KIT; c++) {
        cp_wait<2>();
        __syncthreads();     // stage c ready; all threads done computing c-1

        if (c + 3 < KIT) {   // issue stage c+3 (overwrites buffer (c-1)&3: safe post-sync)
            int s = (c + 3) & 3;
            const __nv_bfloat16* a = gA + (c + 3) * BK;
            const __nv_bfloat16* b = gB + (c + 3) * BK;
            cp16(aBase + s * TILE_B + sOff, a);  cp16(aBase + s * TILE_B + sOff + 16, a + 8);
            cp16(bBase + s * TILE_B + sOff, b);  cp16(bBase + s * TILE_B + sOff + 16, b + 8);
        }
        cp_commit();         // commit every iter to keep group counting consistent

        const __nv_bfloat16* Ab = As + (c & 3) * (TILE_B / 2);
        const __nv_bfloat16* Bb = Bs + (c & 3) * (TILE_B / 2);
#pragma unroll
        for (int kk = 0; kk < 32; kk += 16) {
            uint32_t af[4][4];
#pragma unroll
            for (int i = 0; i < 4; i++) {
                const __nv_bfloat16* p = Ab + (wm + i * 16 + g) * 40 + kk + 2 * q;
                af[i][0] = *(const uint32_t*)p;
                af[i][1] = *(const uint32_t*)(p + 8 * 40);
                af[i][2] = *(const uint32_t*)(p + 8);
                af[i][3] = *(const uint32_t*)(p + 8 * 40 + 8);
            }
#pragma unroll
            for (int j = 0; j < 4; j++) {
                const __nv_bfloat16* p = Bb + (wn + j * 8 + g) * 40 + kk + 2 * q;
                uint32_t b0 = *(const uint32_t*)p;
                uint32_t b1 = *(const uint32_t*)(p + 8);
#pragma unroll
                for (int i = 0; i < 4; i++)
                    mma_bf16(acc[i][j], af[i], b0, b1);
            }
        }
    }

#pragma unroll
    for (int j = 0; j < 4; j++) {
        int n = n0 + wn + j * 8 + 2 * q;
        float b0 = __ldg(bias + bias_off + n);
        float b1 = __ldg(bias + bias_off + n + 1);
#pragma unroll
        for (int i = 0; i < 4; i++) {
            int m = m0 + wm + i * 16 + g;
            float2 v0 = { acc[i][j][0] + b0, acc[i][j][1] + b1 };
            float2 v1 = { acc[i][j][2] + b0, acc[i][j][3] + b1 };
            *(float2*)(g_xproj + (size_t)m * 4096 + n) = v0;
            *(float2*)(g_xproj + (size_t)(m + 8) * 4096 + n) = v1;
        }
    }
}

// ===================================================================
// Phase B: persistent sLSTM recurrence (R8 core + double-buffered
// partials, 1 syncthreads/step, flag publish on named barrier).
// 512 threads; warp = k-split (64 k); lane = gate row; R in regs.
// sH is warp-private (each warp reads only its own staged slice).
// ===================================================================
__global__ __launch_bounds__(512, 1) void slstm_rec(const float* __restrict__ Rl)
{
    extern __shared__ float smem[];
    float* sH    = smem;                 // [1024][16]
    float* sPart = smem + 16384;         // [2][16][PS]

    int tid = threadIdx.x;
    int ks = tid >> 5;
    int lane = tid & 31;
    int u_base = blockIdx.x * 8;

    if (tid == 0) g_flags[blockIdx.x * 8] = 0;
    grid_barrier();

    int grow = (lane >> 3) * 1024 + u_base + (lane & 7);
    const float* rrow = Rl + (size_t)grow * 1024 + ks * 64;
    float Rreg[64];
#pragma unroll
    for (int j = 0; j < 64; j += 4) {
        float4 v = *(const float4*)(rrow + j);
        Rreg[j] = v.x; Rreg[j + 1] = v.y; Rreg[j + 2] = v.z; Rreg[j + 3] = v.w;
    }

    for (int i = tid; i < 16384; i += 512) sH[i] = 0.f;
    __syncthreads();

    // pointwise mapping (tid < 128): b = tid&15, u = tid>>4
    int pb = tid & 15, pu = tid >> 4;
    float creg = 0.f, nreg = 1.f, mreg = 0.f;

    const float* hk = sH + ks * 1024;
    float* pprow0 = sPart + ks * PS + lane * 18;
    const int* myflag = g_flags + (8 * ks + (lane & 7)) * 8;

    for (int t = 0; t < T_STEPS; t++) {
        int pbuf = (t & 1) * (16 * PS);

        float xpre[4];
        if (tid < 128) {
            const float* xp = g_xproj + ((size_t)t * 16 + pb) * 4096 + u_base + pu;
            xpre[0] = __ldg(xp);
            xpre[1] = __ldg(xp + 1024);
            xpre[2] = __ldg(xp + 2048);
            xpre[3] = __ldg(xp + 3072);
        }

        if (t > 0) {
            for (;;) {
                int f;
                asm volatile("ld.acquire.gpu.global.b32 %0, [%1];" : "=r"(f) : "l"(myflag));
                if (__all_sync(0xffffffffu, f >= t)) break;
            }
            const float4* src4 = (const float4*)(g_hbuf[(t - 1) & 1]) + ks * 256 + lane;
            float4* dst4 = (float4*)sH + ks * 256 + lane;
#pragma unroll
            for (int j = 0; j < 8; j++) dst4[j * 32] = __ldcg(src4 + j * 32);
            __syncwarp();
        }

        unsigned long long acc[8];
#pragma unroll
        for (int j = 0; j < 8; j++) acc[j] = 0ull;

#pragma unroll
        for (int k = 0; k < 64; k++) {
            unsigned long long rp = pack2(Rreg[k]);
            const unsigned long long* hp = (const unsigned long long*)(hk + k * 16);
            ulonglong2 h01 = *(const ulonglong2*)(hp + 0);
            ulonglong2 h23 = *(const ulonglong2*)(hp + 2);
            ulonglong2 h45 = *(const ulonglong2*)(hp + 4);
            ulonglong2 h67 = *(const ulonglong2*)(hp + 6);
            fma2(acc[0], rp, h01.x); fma2(acc[1], rp, h01.y);
            fma2(acc[2], rp, h23.x); fma2(acc[3], rp, h23.y);
            fma2(acc[4], rp, h45.x); fma2(acc[5], rp, h45.y);
            fma2(acc[6], rp, h67.x); fma2(acc[7], rp, h67.y);
        }

        float* pprow = pprow0 + pbuf;
#pragma unroll
        for (int j = 0; j < 8; j++)
            *(unsigned long long*)(pprow + j * 2) = acc[j];
        __syncthreads();   // BAR_A: all partials (buffer t&1) ready

        // ---- merged reduce + pointwise + publish (warps 0-3 only) ----
        if (tid < 128) {
            float pre[4];
#pragma unroll
            for (int g4 = 0; g4 < 4; g4++) {
                float s = xpre[g4];
                const float* qp = sPart + pbuf + (g4 * 8 + pu) * 18 + pb;
#pragma unroll
                for (int k2 = 0; k2 < 16; k2++) s += qp[k2 * PS];
                pre[g4] = s;
            }
            float ez = __expf(2.f * pre[0]);
            float z = __fdividef(ez - 1.f, ez + 1.f);
            float o = __fdividef(1.f, 1.f + __expf(-pre[3]));
            float mn = fmaxf(pre[2] + mreg, pre[1]);
            float ip = __expf(pre[1] - mn);
            float fp = __expf(pre[2] + mreg - mn);
            creg = fp * creg + ip * z;
            nreg = fp * nreg + ip;
            mreg = mn;
            float h = o * __fdividef(creg, nreg);
            g_hbuf[t & 1][(u_base + pu) * 16 + pb] = h;
            g_hs[(size_t)pb * 1048576 + (size_t)t * 1024 + u_base + pu] = h;
            asm volatile("bar.sync 1, 128;" ::: "memory");
            if (tid == 0) {
                __threadfence();
                g_flags[blockIdx.x * 8] = t + 1;
            }
        }
        // no BAR_B: sPart is double-buffered; flag transitivity bounds skew to 1 step
    }
}

// ===================================================================
// Final projection: h_last in g_hbuf[(T_STEPS-1)&1] = g_hbuf[1]
// ===================================================================
__global__ __launch_bounds__(256) void final_out(
    const float* __restrict__ Wout, const float* __restrict__ bout,
    float* __restrict__ out)
{
    const float* hsrc = g_hbuf[(T_STEPS - 1) & 1];
    int o = (blockIdx.x * blockDim.x + threadIdx.x) >> 5;
    int lane = threadIdx.x & 31;
    const float* wr = Wout + (size_t)o * 1024;
    float acc[16];
#pragma unroll
    for (int b = 0; b < 16; b++) acc[b] = 0.f;
    for (int k = lane; k < 1024; k += 32) {
        float w = wr[k];
        const float4* hp = (const float4*)(hsrc + k * 16);
        float4 h0 = hp[0], h1 = hp[1], h2 = hp[2], h3 = hp[3];
        acc[0]  += w * h0.x; acc[1]  += w * h0.y; acc[2]  += w * h0.z; acc[3]  += w * h0.w;
        acc[4]  += w * h1.x; acc[5]  += w * h1.y; acc[6]  += w * h1.z; acc[7]  += w * h1.w;
        acc[8]  += w * h2.x; acc[9]  += w * h2.y; acc[10] += w * h2.z; acc[11] += w * h2.w;
        acc[12] += w * h3.x; acc[13] += w * h3.y; acc[14] += w * h3.z; acc[15] += w * h3.w;
    }
#pragma unroll
    for (int b = 0; b < 16; b++) {
#pragma unroll
        for (int off = 16; off; off >>= 1)
            acc[b] += __shfl_down_sync(0xffffffffu, acc[b], off);
    }
    if (lane == 0) {
        float bo = bout[o];
#pragma unroll
        for (int b = 0; b < 16; b++)
            out[(size_t)b * 1024 + o] = acc[b] + bo;
    }
}

// ===================================================================
extern "C" void kernel_launch(void* const* d_in, const int* in_sizes, int n_in,
                              void* d_out, int out_size)
{
    const float* x    = (const float*)d_in[0];
    const float* W    = (const float*)d_in[1];
    const float* R    = (const float*)d_in[2];
    const float* bias = (const float*)d_in[3];
    const float* Wout = (const float*)d_in[4];
    const float* bout = (const float*)d_in[5];
    float* out = (float*)d_out;

    const int REC_SMEM = (16384 + 2 * 16 * PS + 64) * 4;   // 140,544 B
    cudaFuncSetAttribute(slstm_rec, cudaFuncAttributeMaxDynamicSharedMemorySize, REC_SMEM);
    const int GEMM_SMEM = 8 * TILE_B;                       // 81,920 B
    cudaFuncSetAttribute(hmma_gemm, cudaFuncAttributeMaxDynamicSharedMemorySize, GEMM_SMEM);

    __nv_bfloat16 *ga3, *gw3;
    float *ghs;
    cudaGetSymbolAddress((void**)&ga3, g_A3);
    cudaGetSymbolAddress((void**)&gw3, g_W3);
    cudaGetSymbolAddress((void**)&ghs, g_hs);

    dim3 tgrid(32, 128);
    // ---- layer 0 ----
    split3<<<4096, 256>>>(W, gw3, 1024, 2048, 0);
    split3<<<16384, 256>>>(x, ga3, 2048, 1024, 1);
    hmma_gemm<<<tgrid, 256, GEMM_SMEM>>>(bias, 0);
    slstm_rec<<<NCTA, 512, REC_SMEM>>>(R);
    // ---- layer 1 ----
    split3<<<4096, 256>>>(W + (size_t)4096 * 1024, gw3, 1024, 2048, 0);
    split3<<<16384, 256>>>(ghs, ga3, 2048, 1024, 1);
    hmma_gemm<<<tgrid, 256, GEMM_SMEM>>>(bias, 4096);
    slstm_rec<<<NCTA, 512, REC_SMEM>>>(R + (size_t)4096 * 1024);
    // ---- output ----
    final_out<<<128, 256>>>(Wout, bout, out);
}